// round 15
// baseline (speedup 1.0000x reference)
#include <cuda_runtime.h>

#define CH     512
#define HW     4096        // 64*64
#define NPIX   32768       // 8 * 4096

// Static device scratch (no dynamic allocation allowed).
__device__ float g_recon[NPIX];
__device__ float g_ref[NPIX];
__device__ int   g_bar  = 0;   // global barrier arrive counter (self-resetting)
__device__ int   g_bar2 = 0;   // pass counter for the reset

// ---- packed f32x2 helpers (Blackwell FFMA2 path, PTX-only) -----------------
typedef unsigned long long ull;
__device__ __forceinline__ ull pk2(float lo, float hi) {
    ull r; asm("mov.b64 %0, {%1, %2};" : "=l"(r) : "f"(lo), "f"(hi)); return r;
}
__device__ __forceinline__ void unpk2(ull v, float& lo, float& hi) {
    asm("mov.b64 {%0, %1}, %2;" : "=f"(lo), "=f"(hi) : "l"(v));
}
__device__ __forceinline__ ull fma2(ull a, ull b, ull c) {
    ull d; asm("fma.rn.f32x2 %0, %1, %2, %3;" : "=l"(d) : "l"(a), "l"(b), "l"(c));
    return d;
}
__device__ __forceinline__ ull mul2(ull a, ull b) {
    ull d; asm("mul.rn.f32x2 %0, %1, %2;" : "=l"(d) : "l"(a), "l"(b)); return d;
}

// SMEM layout (union of the two phases)
#define SB_BYTES 35648
#define OFF_RS   17680            // Ra: [0, 17680), Rs: [17680, 35360)
#define OFF_SV   35360            // float sv[16][2]
#define OFF_SI   35488            // int   si[16][2]

// ---------------------------------------------------------------------------
// Single kernel, 512 blocks, all resident (launch_bounds(256,4) => 592 slots).
// Phase 1: fused dot+reduce (R6 logic) — every block does DRAM work.
// Global barrier (self-resetting, all-resident => no deadlock).
// Phase 2: k_match v9 (R14 logic).
// ---------------------------------------------------------------------------
__global__ void __launch_bounds__(256, 4) k_all(
        const float* __restrict__ spade, const float* __restrict__ x,
        const float* __restrict__ w1, const float* __restrict__ w2,
        const float* __restrict__ b1, const float* __restrict__ b2,
        float* __restrict__ out) {
    __shared__ __align__(16) char sb[SB_BYTES];
    const int t = threadIdx.x;

    // ======================= PHASE 1: fused dot + reduce ====================
    {
        float2* ws = (float2*)sb;                            // 4 KB
        float4 (*red1)[16] = (float4 (*)[16])(sb + 4096);    // 4 KB
        float4 (*red2)[16] = (float4 (*)[16])(sb + 8192);    // 4 KB

        for (int c = t; c < CH; c += 256) ws[c] = make_float2(w1[c], w2[c]);
        __syncthreads();

        const int pt  = blockIdx.x;               // 64-px tile index (0..511)
        const int b   = pt >> 6;                  // batch
        const int hw0 = (pt & 63) * 64;           // tile base within the image
        const int i   = t & 15;                   // float4 slot (4 px)
        const int j   = t >> 4;                   // channel group (32 ch)

        const size_t base = (size_t)b * CH * HW + (size_t)(j * 32) * HW
                          + hw0 + i * 4;
        const float4* fp = (const float4*)(spade + base);
        const float4* xp = (const float4*)(x + base);
        const float2* wp = ws + j * 32;

        float4 a1 = make_float4(0.f, 0.f, 0.f, 0.f);
        float4 a2 = make_float4(0.f, 0.f, 0.f, 0.f);
        #pragma unroll 8
        for (int c = 0; c < 32; c++) {
            float4 f = __ldcs(fp + (size_t)c * (HW / 4));
            float4 v = __ldcs(xp + (size_t)c * (HW / 4));
            const float2 w = wp[c];
            a1.x += f.x * w.x; a1.y += f.y * w.x;
            a1.z += f.z * w.x; a1.w += f.w * w.x;
            a2.x += v.x * w.y; a2.y += v.y * w.y;
            a2.z += v.z * w.y; a2.w += v.w * w.y;
        }
        red1[j][i] = a1;
        red2[j][i] = a2;
        __syncthreads();

        if (t < 16) {
            float4 s = make_float4(0.f, 0.f, 0.f, 0.f);
            #pragma unroll
            for (int g = 0; g < 16; g++) {
                const float4 a = red1[g][t];
                s.x += a.x; s.y += a.y; s.z += a.z; s.w += a.w;
            }
            const float bb = b1[0];
            s.x = fmaxf(s.x + bb, 0.f); s.y = fmaxf(s.y + bb, 0.f);
            s.z = fmaxf(s.z + bb, 0.f); s.w = fmaxf(s.w + bb, 0.f);
            *(float4*)&g_recon[pt * 64 + t * 4] = s;
            __threadfence();
        } else if (t >= 32 && t < 48) {
            const int i2 = t - 32;
            float4 s = make_float4(0.f, 0.f, 0.f, 0.f);
            #pragma unroll
            for (int g = 0; g < 16; g++) {
                const float4 a = red2[g][i2];
                s.x += a.x; s.y += a.y; s.z += a.z; s.w += a.w;
            }
            const float bb = b2[0];
            s.x = fmaxf(s.x + bb, 0.f); s.y = fmaxf(s.y + bb, 0.f);
            s.z = fmaxf(s.z + bb, 0.f); s.w = fmaxf(s.w + bb, 0.f);
            *(float4*)&g_ref[pt * 64 + i2 * 4] = s;
            __threadfence();
        }
        __syncthreads();
    }

    // ======================= GLOBAL BARRIER (self-resetting) ================
    if (t == 0) {
        atomicAdd(&g_bar, 1);
        while (*(volatile int*)&g_bar < 512) __nanosleep(64);
        __threadfence();                      // acquire: see all phase-1 writes
        const int o2 = atomicAdd(&g_bar2, 1);
        if (o2 == 511) {                      // last passer resets for replay
            atomicExch(&g_bar, 0);
            atomicExch(&g_bar2, 0);
        }
    }
    __syncthreads();

    // ======================= PHASE 2: k_match v9 ============================
    float (*Ra)[68] = (float (*)[68])sb;
    float (*Rs)[68] = (float (*)[68])(sb + OFF_RS);
    float (*sv)[2]  = (float (*)[2])(sb + OFF_SV);
    int   (*si)[2]  = (int   (*)[2])(sb + OFF_SI);

    const int b    = blockIdx.x >> 6;
    const int grp  = blockIdx.x & 63;       // 64 groups of 16 patches
    const float* rb = g_recon + b * HW;

    // ---- vectorized fill ----
    {
        const int r  = t >> 2;              // row 0..63
        const int qx = t & 3;               // 16-col quarter
        const float4* src = (const float4*)(rb + r * 64) + qx * 4;
        const float4 f0 = src[0];
        const float4 f1 = src[1];
        const float4 f2 = src[2];
        const float4 f3 = src[3];
        const float e16 = (qx == 3) ? 0.f : ((const float*)src)[16];
        const int c0 = qx * 16;
        *(float4*)&Ra[r][c0]      = f0;
        *(float4*)&Ra[r][c0 + 4]  = f1;
        *(float4*)&Ra[r][c0 + 8]  = f2;
        *(float4*)&Ra[r][c0 + 12] = f3;
        *(float4*)&Rs[r][c0]      = make_float4(f0.y, f0.z, f0.w, f1.x);
        *(float4*)&Rs[r][c0 + 4]  = make_float4(f1.y, f1.z, f1.w, f2.x);
        *(float4*)&Rs[r][c0 + 8]  = make_float4(f2.y, f2.z, f2.w, f3.x);
        *(float4*)&Rs[r][c0 + 12] = make_float4(f3.y, f3.z, f3.w, e16);
        if (t < 64) {
            *(float4*)&Ra[t][64] = make_float4(0.f, 0.f, 0.f, 0.f);
            *(float4*)&Rs[t][64] = make_float4(0.f, 0.f, 0.f, 0.f);
        }
        if (t >= 64 && t < 81) {
            const int c = (t - 64) * 4;
            *(float4*)&Ra[64][c] = make_float4(0.f, 0.f, 0.f, 0.f);
            *(float4*)&Rs[64][c] = make_float4(0.f, 0.f, 0.f, 0.f);
        }
    }
    __syncthreads();

    const int lane = t & 31;
    const int w    = t >> 5;
    const int rh   = w & 1;                 // row half: rows [rh*32, rh*32+32)
    const int pq   = w >> 1;                // patch quad 0..3
    const float* refb = g_ref + b * HW;

    const int l0 = grp * 16 + pq * 4;       // first of 4 patches for this warp

    ull cc[4][4];
    #pragma unroll
    for (int pp = 0; pp < 4; pp++) {
        const int l  = l0 + pp;
        const int pi = l >> 5, pj = l & 31;
        const float c00 = refb[(2 * pi) * 64 + 2 * pj];
        const float c01 = refb[(2 * pi) * 64 + 2 * pj + 1];
        const float c10 = refb[(2 * pi + 1) * 64 + 2 * pj];
        const float c11 = refb[(2 * pi + 1) * 64 + 2 * pj + 1];
        cc[pp][0] = pk2(c00, c00);
        cc[pp][1] = pk2(c01, c01);
        cc[pp][2] = pk2(c10, c10);
        cc[pp][3] = pk2(c11, c11);
    }

    const int q  = lane * 2;
    const int p0 = rh * 32;

    ull a01 = *(const ull*)&Ra[p0][q];      // rows roll: a=top, b=mid, c=bot
    ull s12 = *(const ull*)&Rs[p0][q];

    float bv[4] = {-1.f, -1.f, -1.f, -1.f};
    int   bi[4] = {0, 0, 0, 0};
    int   idx   = (p0 << 6) + q;            // group-base flat idx

    #pragma unroll 4
    for (int p = p0; p < p0 + 32; p += 2) {
        const ull b01 = *(const ull*)&Ra[p + 1][q];
        const ull t12 = *(const ull*)&Rs[p + 1][q];
        const ull c01 = *(const ull*)&Ra[p + 2][q];
        const ull u12 = *(const ull*)&Rs[p + 2][q];

        #pragma unroll
        for (int pp = 0; pp < 4; pp++) {
            const ull yP = fma2(cc[pp][3], t12, fma2(cc[pp][2], b01,
                           fma2(cc[pp][1], s12, mul2(cc[pp][0], a01))));
            const ull yQ = fma2(cc[pp][3], u12, fma2(cc[pp][2], c01,
                           fma2(cc[pp][1], t12, mul2(cc[pp][0], b01))));
            float p0v, p1v; unpk2(yP, p0v, p1v);
            float q0v, q1v; unpk2(yQ, q0v, q1v);
            const float rv = fmaxf(fmaxf(p0v, p1v), fmaxf(q0v, q1v));
            if (rv > bv[pp]) { bi[pp] = idx; }
            bv[pp] = fmaxf(bv[pp], rv);
        }
        a01 = c01;
        s12 = u12;
        idx += 128;
    }

    // Warp argmax per patch; ties -> smallest group base (row-major order).
    #pragma unroll
    for (int pp = 0; pp < 4; pp++) {
        float v = bv[pp]; int i0 = bi[pp];
        #pragma unroll
        for (int off = 16; off; off >>= 1) {
            const float v2 = __shfl_down_sync(0xffffffffu, v, off);
            const int   i2 = __shfl_down_sync(0xffffffffu, i0, off);
            if (v2 > v || (v2 == v && i2 < i0)) { v = v2; i0 = i2; }
        }
        if (lane == 0) { sv[pq * 4 + pp][rh] = v; si[pq * 4 + pp][rh] = i0; }
    }
    __syncthreads();

    // Combine halves; decode ONLY the winning row (column pair shares the
    // //4 group). Earlier row wins on tie (first occurrence).
    if (t < 16) {
        float v   = sv[t][0];
        int   bw  = si[t][0];
        const float v1 = sv[t][1];
        const int   i1 = si[t][1];
        if (v1 > v) { v = v1; bw = i1; }    // half-1 bases larger -> ties keep half 0

        const int l  = grp * 16 + t;
        const int pi = l >> 5, pj = l & 31;
        const float c00 = refb[(2 * pi) * 64 + 2 * pj];
        const float c01 = refb[(2 * pi) * 64 + 2 * pj + 1];
        const float c10 = refb[(2 * pi + 1) * 64 + 2 * pj];
        const float c11 = refb[(2 * pi + 1) * 64 + 2 * pj + 1];

        const int pr = bw >> 6;              // group top row
        const int qb = bw & 63;              // column pair base
        float y0 = c00 * Ra[pr][qb];
        y0 = fmaf(c01, Rs[pr][qb], y0);
        y0 = fmaf(c10, Ra[pr + 1][qb], y0);
        y0 = fmaf(c11, Rs[pr + 1][qb], y0);
        float y1 = c00 * Ra[pr][qb + 1];
        y1 = fmaf(c01, Rs[pr][qb + 1], y1);
        y1 = fmaf(c10, Ra[pr + 1][qb + 1], y1);
        y1 = fmaf(c11, Rs[pr + 1][qb + 1], y1);
        const int besti = (fmaxf(y0, y1) == v) ? bw : bw + 64;

        const int g  = besti >> 2;           // offset // 4
        const int gi = g >> 5, gj = g & 31;
        float* o = out + b * HW + (2 * pi) * 64 + 2 * pj;
        o[0]  = Ra[2 * gi][2 * gj];
        o[1]  = Ra[2 * gi][2 * gj + 1];
        o[64] = Ra[2 * gi + 1][2 * gj];
        o[65] = Ra[2 * gi + 1][2 * gj + 1];
    }
}

extern "C" void kernel_launch(void* const* d_in, const int* in_sizes, int n_in,
                              void* d_out, int out_size) {
    const float* spade = (const float*)d_in[0];
    const float* x     = (const float*)d_in[1];
    const float* w1    = (const float*)d_in[2];
    const float* b1    = (const float*)d_in[3];
    const float* w2    = (const float*)d_in[4];
    const float* b2    = (const float*)d_in[5];
    float* out = (float*)d_out;

    k_all<<<512, 256>>>(spade, x, w1, w2, b1, b2, out);
}

// round 16
// speedup vs baseline: 1.0589x; 1.0589x over previous
#include <cuda_runtime.h>

#define CH     512
#define HW     4096        // 64*64
#define NPIX   32768       // 8 * 4096

// Static device scratch (no dynamic allocation allowed).
__device__ float g_recon[NPIX];
__device__ float g_ref[NPIX];

// ---- packed f32x2 helpers (Blackwell FFMA2 path, PTX-only) -----------------
typedef unsigned long long ull;
__device__ __forceinline__ ull pk2(float lo, float hi) {
    ull r; asm("mov.b64 %0, {%1, %2};" : "=l"(r) : "f"(lo), "f"(hi)); return r;
}
__device__ __forceinline__ void unpk2(ull v, float& lo, float& hi) {
    asm("mov.b64 {%0, %1}, %2;" : "=f"(lo), "=f"(hi) : "l"(v));
}
__device__ __forceinline__ ull fma2(ull a, ull b, ull c) {
    ull d; asm("fma.rn.f32x2 %0, %1, %2, %3;" : "=l"(d) : "l"(a), "l"(b), "l"(c));
    return d;
}
__device__ __forceinline__ ull mul2(ull a, ull b) {
    ull d; asm("mul.rn.f32x2 %0, %1, %2;" : "=l"(d) : "l"(a), "l"(b)); return d;
}

// ---------------------------------------------------------------------------
// Kernel A (fused dot + reduce) — unchanged from R6 (≈86% of HBM spec).
// ---------------------------------------------------------------------------
__global__ void __launch_bounds__(256) k_fused(
        const float* __restrict__ spade, const float* __restrict__ x,
        const float* __restrict__ w1, const float* __restrict__ w2,
        const float* __restrict__ b1, const float* __restrict__ b2) {
    __shared__ float2 ws[CH];                 // (w1, w2) pairs
    __shared__ float4 red1[16][16];           // [group][float4 slot]
    __shared__ float4 red2[16][16];
    const int t = threadIdx.x;
    for (int c = t; c < CH; c += 256) ws[c] = make_float2(w1[c], w2[c]);
    __syncthreads();

    const int pt  = blockIdx.x;               // 64-px tile index (0..511)
    const int b   = pt >> 6;                  // batch
    const int hw0 = (pt & 63) * 64;           // tile base within the image
    const int i   = t & 15;                   // float4 slot (4 px)
    const int j   = t >> 4;                   // channel group (32 ch)

    const size_t base = (size_t)b * CH * HW + (size_t)(j * 32) * HW + hw0 + i * 4;
    const float4* fp = (const float4*)(spade + base);
    const float4* xp = (const float4*)(x + base);
    const float2* wp = ws + j * 32;

    float4 a1 = make_float4(0.f, 0.f, 0.f, 0.f);
    float4 a2 = make_float4(0.f, 0.f, 0.f, 0.f);
    #pragma unroll 8
    for (int c = 0; c < 32; c++) {
        float4 f = __ldcs(fp + (size_t)c * (HW / 4));
        float4 v = __ldcs(xp + (size_t)c * (HW / 4));
        const float2 w = wp[c];
        a1.x += f.x * w.x; a1.y += f.y * w.x; a1.z += f.z * w.x; a1.w += f.w * w.x;
        a2.x += v.x * w.y; a2.y += v.y * w.y; a2.z += v.z * w.y; a2.w += v.w * w.y;
    }
    red1[j][i] = a1;
    red2[j][i] = a2;
    __syncthreads();

    if (t < 16) {
        float4 s = make_float4(0.f, 0.f, 0.f, 0.f);
        #pragma unroll
        for (int g = 0; g < 16; g++) {
            const float4 a = red1[g][t];
            s.x += a.x; s.y += a.y; s.z += a.z; s.w += a.w;
        }
        const float bb = b1[0];
        s.x = fmaxf(s.x + bb, 0.f); s.y = fmaxf(s.y + bb, 0.f);
        s.z = fmaxf(s.z + bb, 0.f); s.w = fmaxf(s.w + bb, 0.f);
        *(float4*)&g_recon[pt * 64 + t * 4] = s;
    } else if (t >= 32 && t < 48) {
        const int i2 = t - 32;
        float4 s = make_float4(0.f, 0.f, 0.f, 0.f);
        #pragma unroll
        for (int g = 0; g < 16; g++) {
            const float4 a = red2[g][i2];
            s.x += a.x; s.y += a.y; s.z += a.z; s.w += a.w;
        }
        const float bb = b2[0];
        s.x = fmaxf(s.x + bb, 0.f); s.y = fmaxf(s.y + bb, 0.f);
        s.z = fmaxf(s.z + bb, 0.f); s.w = fmaxf(s.w + bb, 0.f);
        *(float4*)&g_ref[pt * 64 + i2 * 4] = s;
    }
}

// ---------------------------------------------------------------------------
// Kernel B (k_match v10 = R14 + 4-row argmax groups):
// Same vectorized fill and 2-row load/FMA structure; the argmax update now
// alternates: even sub-iter stores grp=rv, odd sub-iter folds and does ONE
// guarded (bv, groupBase) update per 4 rows. Decode scans the winning
// group's 4 row-pairs in flat order (bit-exact recompute); column stays
// irrelevant (q,q+1 share the //4 group).
// ---------------------------------------------------------------------------
__global__ void __launch_bounds__(256, 4) k_match(float* __restrict__ out) {
    __shared__ float Ra[65][68];   // recon tile; row 64 / cols>=64 are zero
    __shared__ float Rs[65][68];   // column-shifted tile; same padding
    __shared__ float sv[16][2];    // [local patch][row half] best value
    __shared__ int   si[16][2];    // [local patch][row half] best group base
    const int t    = threadIdx.x;
    const int b    = blockIdx.x >> 6;
    const int grp  = blockIdx.x & 63;       // 64 groups of 16 patches
    const float* rb = g_recon + b * HW;

    // ---- vectorized fill ----
    {
        const int r  = t >> 2;              // row 0..63
        const int qx = t & 3;               // 16-col quarter
        const float4* src = (const float4*)(rb + r * 64) + qx * 4;
        const float4 f0 = src[0];
        const float4 f1 = src[1];
        const float4 f2 = src[2];
        const float4 f3 = src[3];
        const float e16 = (qx == 3) ? 0.f : ((const float*)src)[16];
        const int c0 = qx * 16;
        *(float4*)&Ra[r][c0]      = f0;
        *(float4*)&Ra[r][c0 + 4]  = f1;
        *(float4*)&Ra[r][c0 + 8]  = f2;
        *(float4*)&Ra[r][c0 + 12] = f3;
        *(float4*)&Rs[r][c0]      = make_float4(f0.y, f0.z, f0.w, f1.x);
        *(float4*)&Rs[r][c0 + 4]  = make_float4(f1.y, f1.z, f1.w, f2.x);
        *(float4*)&Rs[r][c0 + 8]  = make_float4(f2.y, f2.z, f2.w, f3.x);
        *(float4*)&Rs[r][c0 + 12] = make_float4(f3.y, f3.z, f3.w, e16);
        if (t < 64) {
            *(float4*)&Ra[t][64] = make_float4(0.f, 0.f, 0.f, 0.f);
            *(float4*)&Rs[t][64] = make_float4(0.f, 0.f, 0.f, 0.f);
        }
        if (t >= 64 && t < 81) {
            const int c = (t - 64) * 4;
            *(float4*)&Ra[64][c] = make_float4(0.f, 0.f, 0.f, 0.f);
            *(float4*)&Rs[64][c] = make_float4(0.f, 0.f, 0.f, 0.f);
        }
    }
    __syncthreads();

    const int lane = t & 31;
    const int w    = t >> 5;
    const int rh   = w & 1;                 // row half: rows [rh*32, rh*32+32)
    const int pq   = w >> 1;                // patch quad 0..3
    const float* refb = g_ref + b * HW;

    const int l0 = grp * 16 + pq * 4;       // first of 4 patches for this warp

    ull cc[4][4];
    #pragma unroll
    for (int pp = 0; pp < 4; pp++) {
        const int l  = l0 + pp;
        const int pi = l >> 5, pj = l & 31;
        const float c00 = refb[(2 * pi) * 64 + 2 * pj];
        const float c01 = refb[(2 * pi) * 64 + 2 * pj + 1];
        const float c10 = refb[(2 * pi + 1) * 64 + 2 * pj];
        const float c11 = refb[(2 * pi + 1) * 64 + 2 * pj + 1];
        cc[pp][0] = pk2(c00, c00);
        cc[pp][1] = pk2(c01, c01);
        cc[pp][2] = pk2(c10, c10);
        cc[pp][3] = pk2(c11, c11);
    }

    const int q  = lane * 2;
    const int p0 = rh * 32;

    ull a01 = *(const ull*)&Ra[p0][q];      // rolling top row
    ull s12 = *(const ull*)&Rs[p0][q];

    float bv[4]  = {-1.f, -1.f, -1.f, -1.f};
    int   bi[4]  = {0, 0, 0, 0};
    float gv[4];                             // 4-row group accumulators
    int   gbase  = (p0 << 6) + q;            // group-base flat idx

    #pragma unroll 4
    for (int g4 = 0; g4 < 8; g4++) {         // 8 groups of 4 rows
        const int p = p0 + g4 * 4;
        // sub-iter 0: rows p, p+1
        {
            const ull b01 = *(const ull*)&Ra[p + 1][q];
            const ull t12 = *(const ull*)&Rs[p + 1][q];
            const ull c01 = *(const ull*)&Ra[p + 2][q];
            const ull u12 = *(const ull*)&Rs[p + 2][q];
            #pragma unroll
            for (int pp = 0; pp < 4; pp++) {
                const ull yP = fma2(cc[pp][3], t12, fma2(cc[pp][2], b01,
                               fma2(cc[pp][1], s12, mul2(cc[pp][0], a01))));
                const ull yQ = fma2(cc[pp][3], u12, fma2(cc[pp][2], c01,
                               fma2(cc[pp][1], t12, mul2(cc[pp][0], b01))));
                float p0v, p1v; unpk2(yP, p0v, p1v);
                float q0v, q1v; unpk2(yQ, q0v, q1v);
                gv[pp] = fmaxf(fmaxf(p0v, p1v), fmaxf(q0v, q1v));
            }
            a01 = c01;
            s12 = u12;
        }
        // sub-iter 1: rows p+2, p+3 — fold + single guarded update
        {
            const ull b01 = *(const ull*)&Ra[p + 3][q];
            const ull t12 = *(const ull*)&Rs[p + 3][q];
            const ull c01 = *(const ull*)&Ra[p + 4][q];
            const ull u12 = *(const ull*)&Rs[p + 4][q];
            #pragma unroll
            for (int pp = 0; pp < 4; pp++) {
                const ull yP = fma2(cc[pp][3], t12, fma2(cc[pp][2], b01,
                               fma2(cc[pp][1], s12, mul2(cc[pp][0], a01))));
                const ull yQ = fma2(cc[pp][3], u12, fma2(cc[pp][2], c01,
                               fma2(cc[pp][1], t12, mul2(cc[pp][0], b01))));
                float p0v, p1v; unpk2(yP, p0v, p1v);
                float q0v, q1v; unpk2(yQ, q0v, q1v);
                const float rv = fmaxf(fmaxf(p0v, p1v), fmaxf(q0v, q1v));
                const float g  = fmaxf(gv[pp], rv);
                if (g > bv[pp]) { bv[pp] = g; bi[pp] = gbase; }
            }
            a01 = c01;
            s12 = u12;
        }
        gbase += 256;                        // 4 rows * 64
    }

    // Warp argmax per patch; ties -> smallest group base (row-major order).
    #pragma unroll
    for (int pp = 0; pp < 4; pp++) {
        float v = bv[pp]; int i0 = bi[pp];
        #pragma unroll
        for (int off = 16; off; off >>= 1) {
            const float v2 = __shfl_down_sync(0xffffffffu, v, off);
            const int   i2 = __shfl_down_sync(0xffffffffu, i0, off);
            if (v2 > v || (v2 == v && i2 < i0)) { v = v2; i0 = i2; }
        }
        if (lane == 0) { sv[pq * 4 + pp][rh] = v; si[pq * 4 + pp][rh] = i0; }
    }
    __syncthreads();

    // Combine halves; decode the winning ROW within the 4-row group (flat
    // order, bit-exact recompute). Column pair shares the //4 group.
    if (t < 16) {
        float v   = sv[t][0];
        int   bw  = si[t][0];
        const float v1 = sv[t][1];
        const int   i1 = si[t][1];
        if (v1 > v) { v = v1; bw = i1; }    // half-1 bases larger -> ties keep half 0

        const int l  = grp * 16 + t;
        const int pi = l >> 5, pj = l & 31;
        const float c00 = refb[(2 * pi) * 64 + 2 * pj];
        const float c01 = refb[(2 * pi) * 64 + 2 * pj + 1];
        const float c10 = refb[(2 * pi + 1) * 64 + 2 * pj];
        const float c11 = refb[(2 * pi + 1) * 64 + 2 * pj + 1];

        const int pr0 = bw >> 6;             // group top row
        const int qb  = bw & 63;             // column pair base
        int besti = bw;
        bool found = false;
        #pragma unroll
        for (int r = 0; r < 4; r++) {
            if (!found) {
                float y0 = c00 * Ra[pr0 + r][qb];
                y0 = fmaf(c01, Rs[pr0 + r][qb], y0);
                y0 = fmaf(c10, Ra[pr0 + r + 1][qb], y0);
                y0 = fmaf(c11, Rs[pr0 + r + 1][qb], y0);
                float y1 = c00 * Ra[pr0 + r][qb + 1];
                y1 = fmaf(c01, Rs[pr0 + r][qb + 1], y1);
                y1 = fmaf(c10, Ra[pr0 + r + 1][qb + 1], y1);
                y1 = fmaf(c11, Rs[pr0 + r + 1][qb + 1], y1);
                if (fmaxf(y0, y1) == v) { besti = bw + r * 64; found = true; }
            }
        }

        const int g  = besti >> 2;           // offset // 4
        const int gi = g >> 5, gj = g & 31;
        float* o = out + b * HW + (2 * pi) * 64 + 2 * pj;
        o[0]  = Ra[2 * gi][2 * gj];
        o[1]  = Ra[2 * gi][2 * gj + 1];
        o[64] = Ra[2 * gi + 1][2 * gj];
        o[65] = Ra[2 * gi + 1][2 * gj + 1];
    }
}

extern "C" void kernel_launch(void* const* d_in, const int* in_sizes, int n_in,
                              void* d_out, int out_size) {
    const float* spade = (const float*)d_in[0];
    const float* x     = (const float*)d_in[1];
    const float* w1    = (const float*)d_in[2];
    const float* b1    = (const float*)d_in[3];
    const float* w2    = (const float*)d_in[4];
    const float* b2    = (const float*)d_in[5];
    float* out = (float*)d_out;

    k_fused<<<512, 256>>>(spade, x, w1, w2, b1, b2);
    k_match<<<512, 256>>>(out);
}